// round 11
// baseline (speedup 1.0000x reference)
#include <cuda_runtime.h>
#include <math.h>

// SymmetricChannel, fused single-kernel.
// Final isolated probe: 8 cols/thread with correct cache policy mix
// (__ldcs msg read-once, __ldg noise for cross-thread L1 sector reuse,
// __stcs out). R3's 8-wide regression was the ldcs-on-noise confound;
// this cell was never measured cleanly.
//
// out[b,l,k] = messages[b,l,k] unless mapped noise column < P:
//   k in [0,253]: zero iff noise[b,l,k+1] < P
//   k == 254   : never zeroed
//   k == 255   : zero iff noise[b,l,0]   < P
// Entropy: sym_ent = entropy + C, ent_copy = entropy, per-b (L=32) warp sums.

#define P_ERR 0.1f

__global__ void __launch_bounds__(256)
chan_fused_kernel(const float* __restrict__ msg,
                  const float* __restrict__ noise,
                  const float* __restrict__ ent,
                  float* __restrict__ out,
                  float* __restrict__ sym_sum,
                  float* __restrict__ sym_ent,
                  float* __restrict__ ent_sum,
                  float* __restrict__ ent_copy,
                  float cst, long n8, long BL) {
    long t = (long)blockIdx.x * blockDim.x + threadIdx.x;
    if (t >= n8) return;

    // Each thread: 8 consecutive columns = 2 float4s.
    long i0 = t * 2;
    float4 m0 = __ldcs(reinterpret_cast<const float4*>(msg) + i0);
    float4 m1 = __ldcs(reinterpret_cast<const float4*>(msg) + i0 + 1);

    // 32 threads per 256-wide row
    long row = t >> 5;
    int k0 = ((int)t & 31) << 3;
    const float* __restrict__ nrow = noise + row * 255;

    float v[8] = {m0.x, m0.y, m0.z, m0.w, m1.x, m1.y, m1.z, m1.w};
#pragma unroll
    for (int c = 0; c < 8; ++c) {
        int k = k0 + c;
        if (k != 254) {
            int nidx = (k == 255) ? 0 : (k + 1);
            // noise: default caching — sectors re-referenced across threads.
            if (__ldg(nrow + nidx) < P_ERR) v[c] = 0.0f;
        }
    }

    __stcs(reinterpret_cast<float4*>(out) + i0,     make_float4(v[0], v[1], v[2], v[3]));
    __stcs(reinterpret_cast<float4*>(out) + i0 + 1, make_float4(v[4], v[5], v[6], v[7]));

    // ---- fused entropy path: first B*L threads (warp == one batch row) ----
    if (t < BL) {
        int lane = (int)t & 31;
        float e = __ldg(ent + t);
        sym_ent[t]  = e + cst;
        ent_copy[t] = e;

        float s = e;
#pragma unroll
        for (int o = 16; o > 0; o >>= 1)
            s += __shfl_xor_sync(0xFFFFFFFFu, s, o);

        if (lane == 0) {
            long b = t >> 5;
            ent_sum[b] = s;
            sym_sum[b] = s + 32.0f * cst;
        }
    }
}

extern "C" void kernel_launch(void* const* d_in, const int* in_sizes, int n_in,
                              void* d_out, int out_size) {
    const float* messages = (const float*)d_in[0];
    const float* entropy  = (const float*)d_in[1];
    const float* noise    = (const float*)d_in[2];

    const long N  = in_sizes[0];          // B*L*V = 33,554,432
    const long BL = in_sizes[1];          // B*L   = 131,072
    const int  L  = 32;
    const int  B  = (int)(BL / L);        // 4096

    float* out      = (float*)d_out;                 // [B,L,V]
    float* sym_sum  = out + N;                       // [B]
    float* sym_ent  = sym_sum + B;                   // [B,L]
    float* ent_sum  = sym_ent + BL;                  // [B]
    float* ent_copy = ent_sum + B;                   // [B,L]

    // const = Hb(p) + log2(V-2)
    const double p = 0.1, q = 0.9;
    const double hb = -(p * log2(p) + q * log2(q));
    const float cst = (float)(hb + log2(254.0));

    const long n8 = N / 8;                // 4,194,304 threads; BL < n8
    const int threads = 256;
    const int blocks = (int)((n8 + threads - 1) / threads);   // 16384
    chan_fused_kernel<<<blocks, threads>>>(messages, noise, entropy, out,
                                           sym_sum, sym_ent, ent_sum, ent_copy,
                                           cst, n8, BL);
}

// round 12
// speedup vs baseline: 1.0094x; 1.0094x over previous
#include <cuda_runtime.h>
#include <math.h>

// SymmetricChannel, fused single-kernel — FINAL (converged, triple-replicated).
// 402 MB compulsory traffic @ ~6.55 TB/s (82-83% of spec, ~93% of measured
// GB300 ceiling). Full config search (R2-R11):
//   width:       4 > 8 (8-wide puts noise lanes 32B apart -> 1 sector/lane ->
//                4x L1 wavefronts per LDG; L1 82% binding, confirmed both
//                with ldcs [R3] and ldg [R11] noise policy)
//   cache:       __ldcs msg (read-once) WIN; __ldcs noise LOSS (kills
//                cross-lane sector reuse); __stcs out neutral-positive
//   persistence: persistent 1-wave grid LOSS on harness replay (R5)
//   block size:  256 ~ 128 > 512 (more CTAs/SM -> better L1tex batching)
//   fusion:      entropy kernel fused into main WIN (-2us, one launch)
//
// out[b,l,k] = messages[b,l,k] unless mapped noise column < P:
//   k in [0,253]: zero iff noise[b,l,k+1] < P
//   k == 254   : never zeroed
//   k == 255   : zero iff noise[b,l,0]   < P
// Entropy: sym_ent = entropy + C, ent_copy = entropy, per-b (L=32) warp sums.

#define P_ERR 0.1f

__global__ void __launch_bounds__(256)
chan_fused_kernel(const float* __restrict__ msg,
                  const float* __restrict__ noise,
                  const float* __restrict__ ent,
                  float* __restrict__ out,
                  float* __restrict__ sym_sum,
                  float* __restrict__ sym_ent,
                  float* __restrict__ ent_sum,
                  float* __restrict__ ent_copy,
                  float cst, long n4, long BL) {
    long i = (long)blockIdx.x * blockDim.x + threadIdx.x;
    if (i >= n4) return;

    // messages: read-once, no reuse anywhere -> evict-first load.
    float4 m = __ldcs(reinterpret_cast<const float4*>(msg) + i);

    // 64 float4 per 256-wide row
    long row = i >> 6;
    int k0 = ((int)i & 63) << 2;
    const float* __restrict__ nrow = noise + row * 255;

    float v[4] = {m.x, m.y, m.z, m.w};
#pragma unroll
    for (int c = 0; c < 4; ++c) {
        int k = k0 + c;
        if (k != 254) {
            int nidx = (k == 255) ? 0 : (k + 1);
            // noise: default caching — 16B lane stride gives 2 lanes/sector reuse.
            if (__ldg(nrow + nidx) < P_ERR) v[c] = 0.0f;
        }
    }

    // Output never re-read: evict-first store.
    __stcs(reinterpret_cast<float4*>(out) + i, make_float4(v[0], v[1], v[2], v[3]));

    // ---- fused entropy path: first B*L threads (warp == one batch row) ----
    if (i < BL) {
        int lane = (int)i & 31;
        float e = __ldg(ent + i);
        sym_ent[i]  = e + cst;
        ent_copy[i] = e;

        float s = e;
#pragma unroll
        for (int o = 16; o > 0; o >>= 1)
            s += __shfl_xor_sync(0xFFFFFFFFu, s, o);

        if (lane == 0) {
            long b = i >> 5;
            ent_sum[b] = s;
            sym_sum[b] = s + 32.0f * cst;
        }
    }
}

extern "C" void kernel_launch(void* const* d_in, const int* in_sizes, int n_in,
                              void* d_out, int out_size) {
    const float* messages = (const float*)d_in[0];
    const float* entropy  = (const float*)d_in[1];
    const float* noise    = (const float*)d_in[2];

    const long N  = in_sizes[0];          // B*L*V = 33,554,432
    const long BL = in_sizes[1];          // B*L   = 131,072
    const int  L  = 32;
    const int  B  = (int)(BL / L);        // 4096

    float* out      = (float*)d_out;                 // [B,L,V]
    float* sym_sum  = out + N;                       // [B]
    float* sym_ent  = sym_sum + B;                   // [B,L]
    float* ent_sum  = sym_ent + BL;                  // [B]
    float* ent_copy = ent_sum + B;                   // [B,L]

    // const = Hb(p) + log2(V-2)
    const double p = 0.1, q = 0.9;
    const double hb = -(p * log2(p) + q * log2(q));
    const float cst = (float)(hb + log2(254.0));

    const long n4 = N / 4;                // 8,388,608 float4 elements
    const int threads = 256;
    const int blocks = (int)((n4 + threads - 1) / threads);   // 32768
    chan_fused_kernel<<<blocks, threads>>>(messages, noise, entropy, out,
                                           sym_sum, sym_ent, ent_sum, ent_copy,
                                           cst, n4, BL);
}